// round 3
// baseline (speedup 1.0000x reference)
#include <cuda_runtime.h>
#include <cuda_bf16.h>
#include <cstdint>

#define N_NODES 50000
#define N_EDGES 800000
#define IN_F    32
#define HF      128   // H*F
#define NH      4
#define FD      32
#define G3      96    // 3*F

// ---------------- scratch (device globals; no runtime allocation) -------------
__device__ __align__(16) float    g_feat[N_NODES * HF];   // (N,128)
__device__ __align__(16) float    g_el  [N_NODES * NH];
__device__ __align__(16) float    g_er  [N_NODES * NH];
__device__ __align__(16) unsigned g_emax[N_NODES * NH];   // ordered-uint encoded float max
__device__ __align__(16) float    g_den [N_NODES * NH];
__device__ __align__(16) float    g_agg [N_NODES * HF];   // unnormalized Σ ee*feat
__device__ __align__(16) float    g_e   [N_EDGES * NH];   // edge logits (post leaky-relu)
__device__ int g_idx64;                                    // 1 if src/dst are int64

// ordered-uint encoding for float atomicMax
__device__ __forceinline__ unsigned fenc(float f) {
    unsigned u = __float_as_uint(f);
    return (u & 0x80000000u) ? ~u : (u | 0x80000000u);
}
__device__ __forceinline__ float fdec(unsigned u) {
    return (u & 0x80000000u) ? __uint_as_float(u & 0x7fffffffu) : __uint_as_float(~u);
}

// load node index e from a buffer that is either int32 or int64
__device__ __forceinline__ int ldidx(const void* p, int e, int is64) {
    return is64 ? (int)((const long long*)p)[e] : ((const int*)p)[e];
}

// ---------------- K-1: dtype probe -------------------------------------------
// int64 values < 2^31 have zero odd 32-bit words (little endian).
__global__ void k_probe(const unsigned* __restrict__ raw) {
    unsigned any = 0;
#pragma unroll
    for (int i = 1; i < 256; i += 2) any |= raw[i];
    g_idx64 = (any == 0u) ? 1 : 0;
}

// ---------------- K0: init scratch -------------------------------------------
__global__ void k_init() {
    int i = blockIdx.x * blockDim.x + threadIdx.x;
    if (i < N_NODES * HF) g_agg[i] = 0.0f;
    if (i < N_NODES * NH) { g_emax[i] = 0u; g_den[i] = 0.0f; }
}

// ---------------- K1: feat = h@W_gat, el, er ----------------------------------
__global__ void __launch_bounds__(128) k_feat(
    const float* __restrict__ h, const float* __restrict__ Wg,
    const float* __restrict__ al, const float* __restrict__ ar)
{
    __shared__ float Ws[IN_F * HF];   // 16 KB
    __shared__ float hsm[64 * IN_F];  // 8 KB
    int t = threadIdx.x;
    for (int i = t; i < IN_F * HF; i += 128) Ws[i] = Wg[i];
    float a_l = al[t];   // (H,F) flattened; t = head*32+f
    float a_r = ar[t];
    int base = blockIdx.x * 64;
    for (int i = t; i < 64 * IN_F; i += 128) {
        int n = base + (i >> 5);
        hsm[i] = (n < N_NODES) ? h[n * IN_F + (i & 31)] : 0.0f;
    }
    __syncthreads();
    int lane = t & 31, w = t >> 5;
    for (int j = 0; j < 64; j++) {
        int n = base + j;
        if (n >= N_NODES) break;
        float acc = 0.0f;
#pragma unroll
        for (int k = 0; k < IN_F; k++) acc = fmaf(hsm[j * IN_F + k], Ws[k * HF + t], acc);
        g_feat[n * HF + t] = acc;
        float pl = acc * a_l, pr = acc * a_r;
#pragma unroll
        for (int o = 16; o; o >>= 1) {
            pl += __shfl_down_sync(0xffffffffu, pl, o);
            pr += __shfl_down_sync(0xffffffffu, pr, o);
        }
        if (lane == 0) { g_el[n * NH + w] = pl; g_er[n * NH + w] = pr; }
    }
}

// ---------------- K2: edge logits + segment max -------------------------------
__global__ void __launch_bounds__(256) k_edge(
    const void* __restrict__ src, const void* __restrict__ dst)
{
    int e = blockIdx.x * blockDim.x + threadIdx.x;
    if (e >= N_EDGES) return;
    int is64 = g_idx64;
    int s = ldidx(src, e, is64), d = ldidx(dst, e, is64);
    float4 a = *(const float4*)&g_el[s * NH];
    float4 b = *(const float4*)&g_er[d * NH];
    float4 v; float x;
    x = a.x + b.x; v.x = x > 0.f ? x : 0.2f * x;
    x = a.y + b.y; v.y = x > 0.f ? x : 0.2f * x;
    x = a.z + b.z; v.z = x > 0.f ? x : 0.2f * x;
    x = a.w + b.w; v.w = x > 0.f ? x : 0.2f * x;
    *(float4*)&g_e[e * NH] = v;
    atomicMax(&g_emax[d * NH + 0], fenc(v.x));
    atomicMax(&g_emax[d * NH + 1], fenc(v.y));
    atomicMax(&g_emax[d * NH + 2], fenc(v.z));
    atomicMax(&g_emax[d * NH + 3], fenc(v.w));
}

// ---------------- K3: fused exp + weighted scatter + denom --------------------
// warp per edge; lane l handles feat columns [4l,4l+4), head = l>>3
__global__ void __launch_bounds__(256) k_agg(
    const void* __restrict__ src, const void* __restrict__ dst)
{
    int e = blockIdx.x * 8 + (threadIdx.x >> 5);
    int lane = threadIdx.x & 31;
    if (e >= N_EDGES) return;
    int is64 = g_idx64;
    int s = ldidx(src, e, is64), d = ldidx(dst, e, is64);
    float4 ev = *(const float4*)&g_e[e * NH];
    int hd = lane >> 3;
    float evh = (hd < 2) ? (hd ? ev.y : ev.x) : (hd == 3 ? ev.w : ev.z);
    float mh = fdec(g_emax[d * NH + hd]);
    float ee = __expf(evh - mh);
    float4 f4 = *(const float4*)&g_feat[s * HF + lane * 4];
    float* p = &g_agg[d * HF + lane * 4];
    asm volatile("red.global.add.v4.f32 [%0], {%1,%2,%3,%4};"
                 :: "l"(p), "f"(f4.x * ee), "f"(f4.y * ee), "f"(f4.z * ee), "f"(f4.w * ee)
                 : "memory");
    if ((lane & 7) == 0) atomicAdd(&g_den[d * NH + hd], ee);
}

// ---------------- K4: GRU cell + ELU ------------------------------------------
#define W_PAD   132
#define WH_PAD  36
#define NODES_B 32

__global__ void __launch_bounds__(256) k_gru(
    const float* __restrict__ h,
    const float* __restrict__ Wih, const float* __restrict__ Whh,
    const float* __restrict__ bih, const float* __restrict__ bhh,
    float* __restrict__ out)
{
    extern __shared__ float sm[];
    float* sWih = sm;                         // [96][132]
    float* sWhh = sWih + G3 * W_PAD;          // [96][36]
    float* sbi  = sWhh + G3 * WH_PAD;         // 96
    float* sbh  = sbi + G3;                   // 96
    float* xs   = sbh + G3;                   // [32][128]
    float* hs   = xs + NODES_B * HF;          // [32][32]

    int t = threadIdx.x;
    for (int i = t; i < G3 * HF; i += 256) sWih[(i >> 7) * W_PAD + (i & 127)] = Wih[i];
    for (int i = t; i < G3 * FD; i += 256) sWhh[(i >> 5) * WH_PAD + (i & 31)] = Whh[i];
    if (t < G3) { sbi[t] = bih[t]; sbh[t] = bhh[t]; }

    int base = blockIdx.x * NODES_B;
    for (int i = t; i < NODES_B * HF; i += 256) {
        int j = i >> 7, n = base + j, c = i & 127;
        float v = 0.0f;
        if (n < N_NODES) {
            float dn = g_den[n * NH + (c >> 5)];
            v = (dn > 0.0f) ? g_agg[n * HF + c] / dn : 0.0f;
        }
        xs[i] = v;
    }
    for (int i = t; i < NODES_B * FD; i += 256) {
        int n = base + (i >> 5);
        hs[i] = (n < N_NODES) ? h[n * FD + (i & 31)] : 0.0f;
    }
    __syncthreads();

    int oi = t & 31, ni = t >> 5;
    float gr[4], gz[4], gn[4], hr[4], hz[4], hn[4];
#pragma unroll
    for (int j = 0; j < 4; j++) {
        gr[j] = sbi[oi]; gz[j] = sbi[32 + oi]; gn[j] = sbi[64 + oi];
        hr[j] = sbh[oi]; hz[j] = sbh[32 + oi]; hn[j] = sbh[64 + oi];
    }
    for (int k = 0; k < HF; k += 4) {
        float4 w0 = *(const float4*)&sWih[oi * W_PAD + k];
        float4 w1 = *(const float4*)&sWih[(32 + oi) * W_PAD + k];
        float4 w2 = *(const float4*)&sWih[(64 + oi) * W_PAD + k];
#pragma unroll
        for (int j = 0; j < 4; j++) {
            float4 xv = *(const float4*)&xs[(ni * 4 + j) * HF + k];
            gr[j] = fmaf(w0.x, xv.x, fmaf(w0.y, xv.y, fmaf(w0.z, xv.z, fmaf(w0.w, xv.w, gr[j]))));
            gz[j] = fmaf(w1.x, xv.x, fmaf(w1.y, xv.y, fmaf(w1.z, xv.z, fmaf(w1.w, xv.w, gz[j]))));
            gn[j] = fmaf(w2.x, xv.x, fmaf(w2.y, xv.y, fmaf(w2.z, xv.z, fmaf(w2.w, xv.w, gn[j]))));
        }
    }
    for (int k = 0; k < FD; k += 4) {
        float4 w0 = *(const float4*)&sWhh[oi * WH_PAD + k];
        float4 w1 = *(const float4*)&sWhh[(32 + oi) * WH_PAD + k];
        float4 w2 = *(const float4*)&sWhh[(64 + oi) * WH_PAD + k];
#pragma unroll
        for (int j = 0; j < 4; j++) {
            float4 hv = *(const float4*)&hs[(ni * 4 + j) * FD + k];
            hr[j] = fmaf(w0.x, hv.x, fmaf(w0.y, hv.y, fmaf(w0.z, hv.z, fmaf(w0.w, hv.w, hr[j]))));
            hz[j] = fmaf(w1.x, hv.x, fmaf(w1.y, hv.y, fmaf(w1.z, hv.z, fmaf(w1.w, hv.w, hz[j]))));
            hn[j] = fmaf(w2.x, hv.x, fmaf(w2.y, hv.y, fmaf(w2.z, hv.z, fmaf(w2.w, hv.w, hn[j]))));
        }
    }
#pragma unroll
    for (int j = 0; j < 4; j++) {
        int n = base + ni * 4 + j;
        if (n >= N_NODES) continue;
        float r  = 1.0f / (1.0f + expf(-(gr[j] + hr[j])));
        float z  = 1.0f / (1.0f + expf(-(gz[j] + hz[j])));
        float nn = tanhf(gn[j] + r * hn[j]);
        float hv = hs[(ni * 4 + j) * FD + oi];
        float hnew = (1.0f - z) * nn + z * hv;
        out[n * FD + oi] = hnew > 0.0f ? hnew : (expf(hnew) - 1.0f);
    }
}

// ---------------- launch -------------------------------------------------------
extern "C" void kernel_launch(void* const* d_in, const int* in_sizes, int n_in,
                              void* d_out, int out_size)
{
    const float* h    = (const float*)d_in[0];
    const float* Wg   = (const float*)d_in[1];
    const float* al   = (const float*)d_in[2];
    const float* ar   = (const float*)d_in[3];
    const float* Wih  = (const float*)d_in[4];
    const float* Whh  = (const float*)d_in[5];
    const float* bih  = (const float*)d_in[6];
    const float* bhh  = (const float*)d_in[7];
    const void*  src  = d_in[8];
    const void*  dst  = d_in[9];
    float* out = (float*)d_out;

    static bool attr_set = false;
    size_t gru_smem = (size_t)(G3 * W_PAD + G3 * WH_PAD + 2 * G3 +
                               NODES_B * HF + NODES_B * FD) * sizeof(float);
    if (!attr_set) {
        cudaFuncSetAttribute(k_gru, cudaFuncAttributeMaxDynamicSharedMemorySize, (int)gru_smem);
        attr_set = true;
    }

    k_probe<<<1, 1>>>((const unsigned*)dst);
    k_init<<<(N_NODES * HF + 255) / 256, 256>>>();
    k_feat<<<(N_NODES + 63) / 64, 128>>>(h, Wg, al, ar);
    k_edge<<<(N_EDGES + 255) / 256, 256>>>(src, dst);
    k_agg<<<(N_EDGES + 7) / 8, 256>>>(src, dst);
    k_gru<<<(N_NODES + NODES_B - 1) / NODES_B, 256, gru_smem>>>(h, Wih, Whh, bih, bhh, out);
}

// round 4
// speedup vs baseline: 1.0703x; 1.0703x over previous
#include <cuda_runtime.h>
#include <cuda_bf16.h>
#include <cstdint>

#define N_NODES 50000
#define N_EDGES 800000
#define IN_F    32
#define HF      128   // H*F
#define NH      4
#define FD      32
#define G3      96    // 3*F

// ---------------- scratch (device globals) ------------------------------------
__device__ __align__(16) float g_feat[N_NODES * HF];   // (N,128)
__device__ __align__(16) float g_el  [N_NODES * NH];
__device__ __align__(16) float g_er  [N_NODES * NH];
__device__ __align__(16) float g_x   [N_NODES * HF];   // normalized agg = GRU input
__device__ int g_cnt [N_NODES];                         // histogram, then fill-cursor
__device__ int g_rowp[N_NODES + 1];
__device__ int g_csrc[N_EDGES];                         // src node per CSR slot
__device__ int g_idx64;

// load node index e from a buffer that is either int32 or int64
__device__ __forceinline__ int ldidx(const void* p, int e, int is64) {
    return is64 ? (int)((const long long*)p)[e] : ((const int*)p)[e];
}

// ---------------- dtype probe --------------------------------------------------
__global__ void k_probe(const unsigned* __restrict__ raw) {
    unsigned any = 0;
#pragma unroll
    for (int i = 1; i < 256; i += 2) any |= raw[i];
    g_idx64 = (any == 0u) ? 1 : 0;
}

// ---------------- CSR build ----------------------------------------------------
__global__ void k_zero() {
    int i = blockIdx.x * blockDim.x + threadIdx.x;
    if (i < N_NODES) g_cnt[i] = 0;
}

__global__ void __launch_bounds__(256) k_hist(const void* __restrict__ dst) {
    int e = blockIdx.x * blockDim.x + threadIdx.x;
    if (e >= N_EDGES) return;
    atomicAdd(&g_cnt[ldidx(dst, e, g_idx64)], 1);
}

// single-block exclusive scan over 50k counts; writes row_ptr and resets cursor
__global__ void __launch_bounds__(1024) k_scan() {
    const int C = (N_NODES + 1023) / 1024;   // 49
    int t = threadIdx.x, lane = t & 31, wid = t >> 5;
    int base = t * C;
    int s = 0;
    for (int i = 0; i < C; i++) {
        int idx = base + i;
        if (idx < N_NODES) s += g_cnt[idx];
    }
    // inclusive warp scan
    int v = s;
#pragma unroll
    for (int o = 1; o < 32; o <<= 1) {
        int n = __shfl_up_sync(0xffffffffu, v, o);
        if (lane >= o) v += n;
    }
    __shared__ int wsum[32];
    if (lane == 31) wsum[wid] = v;
    __syncthreads();
    if (wid == 0) {
        int w = wsum[lane];
#pragma unroll
        for (int o = 1; o < 32; o <<= 1) {
            int n = __shfl_up_sync(0xffffffffu, w, o);
            if (lane >= o) w += n;
        }
        wsum[lane] = w;
    }
    __syncthreads();
    int run = v - s + (wid ? wsum[wid - 1] : 0);   // exclusive prefix for this thread
    for (int i = 0; i < C; i++) {
        int idx = base + i;
        if (idx < N_NODES) {
            int c = g_cnt[idx];
            g_rowp[idx] = run;
            g_cnt[idx]  = run;   // cursor for fill
            run += c;
        }
    }
    if (t == 0) g_rowp[N_NODES] = N_EDGES;
}

__global__ void __launch_bounds__(256) k_fill(
    const void* __restrict__ src, const void* __restrict__ dst)
{
    int e = blockIdx.x * blockDim.x + threadIdx.x;
    if (e >= N_EDGES) return;
    int is64 = g_idx64;
    int d = ldidx(dst, e, is64);
    int pos = atomicAdd(&g_cnt[d], 1);
    g_csrc[pos] = ldidx(src, e, is64);
}

// ---------------- K1: feat = h@W_gat, el, er ----------------------------------
__global__ void __launch_bounds__(128) k_feat(
    const float* __restrict__ h, const float* __restrict__ Wg,
    const float* __restrict__ al, const float* __restrict__ ar)
{
    __shared__ float Ws[IN_F * HF];   // 16 KB
    __shared__ float hsm[64 * IN_F];  // 8 KB
    int t = threadIdx.x;
    for (int i = t; i < IN_F * HF; i += 128) Ws[i] = Wg[i];
    float a_l = al[t];
    float a_r = ar[t];
    int base = blockIdx.x * 64;
    for (int i = t; i < 64 * IN_F; i += 128) {
        int n = base + (i >> 5);
        hsm[i] = (n < N_NODES) ? h[n * IN_F + (i & 31)] : 0.0f;
    }
    __syncthreads();
    int lane = t & 31, w = t >> 5;
    for (int j = 0; j < 64; j++) {
        int n = base + j;
        if (n >= N_NODES) break;
        float acc = 0.0f;
#pragma unroll
        for (int k = 0; k < IN_F; k++) acc = fmaf(hsm[j * IN_F + k], Ws[k * HF + t], acc);
        g_feat[n * HF + t] = acc;
        float pl = acc * a_l, pr = acc * a_r;
#pragma unroll
        for (int o = 16; o; o >>= 1) {
            pl += __shfl_down_sync(0xffffffffu, pl, o);
            pr += __shfl_down_sync(0xffffffffu, pr, o);
        }
        if (lane == 0) { g_el[n * NH + w] = pl; g_er[n * NH + w] = pr; }
    }
}

// ---------------- K2: CSR softmax-aggregate (warp per dst node) ----------------
__device__ __forceinline__ float lrelu(float x) { return x > 0.f ? x : 0.2f * x; }

__global__ void __launch_bounds__(256) k_aggr() {
    int n = blockIdx.x * 8 + (threadIdx.x >> 5);
    if (n >= N_NODES) return;
    int lane = threadIdx.x & 31;
    int beg = g_rowp[n], end = g_rowp[n + 1];
    int hd = lane >> 3;
    float4 er4 = *(const float4*)&g_er[n * NH];    // broadcast

    // pass A: per-head max
    float4 mx = make_float4(-1e30f, -1e30f, -1e30f, -1e30f);
    for (int j = beg + lane; j < end; j += 32) {
        int s = g_csrc[j];
        float4 el4 = *(const float4*)&g_el[s * NH];
        mx.x = fmaxf(mx.x, lrelu(el4.x + er4.x));
        mx.y = fmaxf(mx.y, lrelu(el4.y + er4.y));
        mx.z = fmaxf(mx.z, lrelu(el4.z + er4.z));
        mx.w = fmaxf(mx.w, lrelu(el4.w + er4.w));
    }
#pragma unroll
    for (int o = 16; o; o >>= 1) {
        mx.x = fmaxf(mx.x, __shfl_xor_sync(0xffffffffu, mx.x, o));
        mx.y = fmaxf(mx.y, __shfl_xor_sync(0xffffffffu, mx.y, o));
        mx.z = fmaxf(mx.z, __shfl_xor_sync(0xffffffffu, mx.z, o));
        mx.w = fmaxf(mx.w, __shfl_xor_sync(0xffffffffu, mx.w, o));
    }

    // pass B: denominators
    float4 dn = make_float4(0.f, 0.f, 0.f, 0.f);
    for (int j = beg + lane; j < end; j += 32) {
        int s = g_csrc[j];
        float4 el4 = *(const float4*)&g_el[s * NH];
        dn.x += __expf(lrelu(el4.x + er4.x) - mx.x);
        dn.y += __expf(lrelu(el4.y + er4.y) - mx.y);
        dn.z += __expf(lrelu(el4.z + er4.z) - mx.z);
        dn.w += __expf(lrelu(el4.w + er4.w) - mx.w);
    }
#pragma unroll
    for (int o = 16; o; o >>= 1) {
        dn.x += __shfl_xor_sync(0xffffffffu, dn.x, o);
        dn.y += __shfl_xor_sync(0xffffffffu, dn.y, o);
        dn.z += __shfl_xor_sync(0xffffffffu, dn.z, o);
        dn.w += __shfl_xor_sync(0xffffffffu, dn.w, o);
    }

    float er_h = (hd < 2) ? (hd ? er4.y : er4.x) : (hd == 3 ? er4.w : er4.z);
    float mx_h = (hd < 2) ? (hd ? mx.y : mx.x) : (hd == 3 ? mx.w : mx.z);
    float dn_h = (hd < 2) ? (hd ? dn.y : dn.x) : (hd == 3 ? dn.w : dn.z);
    float inv  = (dn_h > 0.f) ? __frcp_rn(dn_h) : 0.0f;

    // pass C: warp-uniform edge loop, lane handles feat cols [4l, 4l+4)
    float4 acc = make_float4(0.f, 0.f, 0.f, 0.f);
    for (int j = beg; j < end; j++) {
        int s = g_csrc[j];                        // broadcast
        float ee = __expf(lrelu(g_el[s * NH + hd] + er_h) - mx_h);
        float4 f = *(const float4*)&g_feat[s * HF + lane * 4];
        acc.x = fmaf(f.x, ee, acc.x);
        acc.y = fmaf(f.y, ee, acc.y);
        acc.z = fmaf(f.z, ee, acc.z);
        acc.w = fmaf(f.w, ee, acc.w);
    }
    acc.x *= inv; acc.y *= inv; acc.z *= inv; acc.w *= inv;
    *(float4*)&g_x[n * HF + lane * 4] = acc;
}

// ---------------- K4: GRU cell + ELU ------------------------------------------
#define W_PAD   132
#define WH_PAD  36
#define NODES_B 32

__global__ void __launch_bounds__(256) k_gru(
    const float* __restrict__ h,
    const float* __restrict__ Wih, const float* __restrict__ Whh,
    const float* __restrict__ bih, const float* __restrict__ bhh,
    float* __restrict__ out)
{
    extern __shared__ float sm[];
    float* sWih = sm;                         // [96][132]
    float* sWhh = sWih + G3 * W_PAD;          // [96][36]
    float* sbi  = sWhh + G3 * WH_PAD;         // 96
    float* sbh  = sbi + G3;                   // 96
    float* xs   = sbh + G3;                   // [32][128]
    float* hs   = xs + NODES_B * HF;          // [32][32]

    int t = threadIdx.x;
    for (int i = t; i < G3 * HF; i += 256) sWih[(i >> 7) * W_PAD + (i & 127)] = Wih[i];
    for (int i = t; i < G3 * FD; i += 256) sWhh[(i >> 5) * WH_PAD + (i & 31)] = Whh[i];
    if (t < G3) { sbi[t] = bih[t]; sbh[t] = bhh[t]; }

    int base = blockIdx.x * NODES_B;
    for (int i = t; i < NODES_B * HF; i += 256) {
        int n = base + (i >> 7);
        xs[i] = (n < N_NODES) ? g_x[n * HF + (i & 127)] : 0.0f;
    }
    for (int i = t; i < NODES_B * FD; i += 256) {
        int n = base + (i >> 5);
        hs[i] = (n < N_NODES) ? h[n * FD + (i & 31)] : 0.0f;
    }
    __syncthreads();

    int oi = t & 31, ni = t >> 5;
    float gr[4], gz[4], gn[4], hr[4], hz[4], hn[4];
#pragma unroll
    for (int j = 0; j < 4; j++) {
        gr[j] = sbi[oi]; gz[j] = sbi[32 + oi]; gn[j] = sbi[64 + oi];
        hr[j] = sbh[oi]; hz[j] = sbh[32 + oi]; hn[j] = sbh[64 + oi];
    }
    for (int k = 0; k < HF; k += 4) {
        float4 w0 = *(const float4*)&sWih[oi * W_PAD + k];
        float4 w1 = *(const float4*)&sWih[(32 + oi) * W_PAD + k];
        float4 w2 = *(const float4*)&sWih[(64 + oi) * W_PAD + k];
#pragma unroll
        for (int j = 0; j < 4; j++) {
            float4 xv = *(const float4*)&xs[(ni * 4 + j) * HF + k];
            gr[j] = fmaf(w0.x, xv.x, fmaf(w0.y, xv.y, fmaf(w0.z, xv.z, fmaf(w0.w, xv.w, gr[j]))));
            gz[j] = fmaf(w1.x, xv.x, fmaf(w1.y, xv.y, fmaf(w1.z, xv.z, fmaf(w1.w, xv.w, gz[j]))));
            gn[j] = fmaf(w2.x, xv.x, fmaf(w2.y, xv.y, fmaf(w2.z, xv.z, fmaf(w2.w, xv.w, gn[j]))));
        }
    }
    for (int k = 0; k < FD; k += 4) {
        float4 w0 = *(const float4*)&sWhh[oi * WH_PAD + k];
        float4 w1 = *(const float4*)&sWhh[(32 + oi) * WH_PAD + k];
        float4 w2 = *(const float4*)&sWhh[(64 + oi) * WH_PAD + k];
#pragma unroll
        for (int j = 0; j < 4; j++) {
            float4 hv = *(const float4*)&hs[(ni * 4 + j) * FD + k];
            hr[j] = fmaf(w0.x, hv.x, fmaf(w0.y, hv.y, fmaf(w0.z, hv.z, fmaf(w0.w, hv.w, hr[j]))));
            hz[j] = fmaf(w1.x, hv.x, fmaf(w1.y, hv.y, fmaf(w1.z, hv.z, fmaf(w1.w, hv.w, hz[j]))));
            hn[j] = fmaf(w2.x, hv.x, fmaf(w2.y, hv.y, fmaf(w2.z, hv.z, fmaf(w2.w, hv.w, hn[j]))));
        }
    }
#pragma unroll
    for (int j = 0; j < 4; j++) {
        int n = base + ni * 4 + j;
        if (n >= N_NODES) continue;
        float r  = 1.0f / (1.0f + expf(-(gr[j] + hr[j])));
        float z  = 1.0f / (1.0f + expf(-(gz[j] + hz[j])));
        float nn = tanhf(gn[j] + r * hn[j]);
        float hv = hs[(ni * 4 + j) * FD + oi];
        float hnew = (1.0f - z) * nn + z * hv;
        out[n * FD + oi] = hnew > 0.0f ? hnew : (expf(hnew) - 1.0f);
    }
}

// ---------------- launch -------------------------------------------------------
extern "C" void kernel_launch(void* const* d_in, const int* in_sizes, int n_in,
                              void* d_out, int out_size)
{
    const float* h    = (const float*)d_in[0];
    const float* Wg   = (const float*)d_in[1];
    const float* al   = (const float*)d_in[2];
    const float* ar   = (const float*)d_in[3];
    const float* Wih  = (const float*)d_in[4];
    const float* Whh  = (const float*)d_in[5];
    const float* bih  = (const float*)d_in[6];
    const float* bhh  = (const float*)d_in[7];
    const void*  src  = d_in[8];
    const void*  dst  = d_in[9];
    float* out = (float*)d_out;

    static bool attr_set = false;
    size_t gru_smem = (size_t)(G3 * W_PAD + G3 * WH_PAD + 2 * G3 +
                               NODES_B * HF + NODES_B * FD) * sizeof(float);
    if (!attr_set) {
        cudaFuncSetAttribute(k_gru, cudaFuncAttributeMaxDynamicSharedMemorySize, (int)gru_smem);
        attr_set = true;
    }

    k_probe<<<1, 1>>>((const unsigned*)dst);
    k_zero <<<(N_NODES + 255) / 256, 256>>>();
    k_feat <<<(N_NODES + 63) / 64, 128>>>(h, Wg, al, ar);
    k_hist <<<(N_EDGES + 255) / 256, 256>>>(dst);
    k_scan <<<1, 1024>>>();
    k_fill <<<(N_EDGES + 255) / 256, 256>>>(src, dst);
    k_aggr <<<(N_NODES + 7) / 8, 256>>>();
    k_gru  <<<(N_NODES + NODES_B - 1) / NODES_B, 256, gru_smem>>>(h, Wih, Whh, bih, bhh, out);
}

// round 5
// speedup vs baseline: 1.2294x; 1.1486x over previous
#include <cuda_runtime.h>
#include <cuda_bf16.h>
#include <cstdint>

#define N_NODES 50000
#define N_EDGES 800000
#define IN_F    32
#define HF      128   // H*F
#define NH      4
#define FD      32
#define G3      96    // 3*F

// ---------------- scratch (device globals) ------------------------------------
__device__ __align__(16) float g_feat[N_NODES * HF];   // (N,128)
__device__ __align__(16) float g_el  [N_NODES * NH];
__device__ __align__(16) float g_er  [N_NODES * NH];
__device__ __align__(16) float g_x   [N_NODES * HF];   // normalized agg = GRU input
__device__ int g_cnt [N_NODES];                         // histogram, then fill-cursor
__device__ int g_rowp[N_NODES + 1];
__device__ int g_csrc[N_EDGES];                         // src node per CSR slot
__device__ int g_idx64;

__device__ __forceinline__ int ldidx(const void* p, int e, int is64) {
    return is64 ? (int)((const long long*)p)[e] : ((const int*)p)[e];
}
__device__ __forceinline__ float lrelu(float x) { return x > 0.f ? x : 0.2f * x; }

// ---------------- K0: probe dtype + zero counters ------------------------------
__global__ void k_init(const unsigned* __restrict__ raw) {
    int i = blockIdx.x * blockDim.x + threadIdx.x;
    if (i < N_NODES) g_cnt[i] = 0;
    if (blockIdx.x == 0 && threadIdx.x == 0) {
        unsigned any = 0;
#pragma unroll
        for (int k = 1; k < 256; k += 2) any |= raw[k];
        g_idx64 = (any == 0u) ? 1 : 0;
    }
}

// ---------------- K1: fused feat-GEMM (+el/er) AND dst histogram ---------------
#define FEAT_BLOCKS 391   // ceil(50000/128)
__global__ void __launch_bounds__(256) k_feathist(
    const float* __restrict__ h, const float* __restrict__ Wg,
    const float* __restrict__ al, const float* __restrict__ ar,
    const void* __restrict__ dst)
{
    __shared__ float Ws[IN_F * HF];     // 16 KB
    __shared__ float hsm[128 * IN_F];   // 16 KB
    int t = threadIdx.x;
    if (blockIdx.x >= FEAT_BLOCKS) {
        // histogram part
        int e = (blockIdx.x - FEAT_BLOCKS) * 256 + t;
        if (e < N_EDGES) atomicAdd(&g_cnt[ldidx(dst, e, g_idx64)], 1);
        return;
    }
    // feat part: 128 nodes per block; threads split into two 128-thread halves
    for (int i = t; i < IN_F * HF; i += 256) Ws[i] = Wg[i];
    int tc = t & 127, half = t >> 7;
    float a_l = al[tc], a_r = ar[tc];
    int nb = blockIdx.x * 128;
    for (int i = t; i < 128 * IN_F; i += 256) {
        int n = nb + (i >> 5);
        hsm[i] = (n < N_NODES) ? h[n * IN_F + (i & 31)] : 0.0f;
    }
    __syncthreads();
    int lane = t & 31, w = tc >> 5;   // head index
    int lbase = half * 64;
    for (int j = 0; j < 64; j++) {
        int n = nb + lbase + j;
        if (n >= N_NODES) break;
        float acc = 0.0f;
#pragma unroll
        for (int k = 0; k < IN_F; k++)
            acc = fmaf(hsm[(lbase + j) * IN_F + k], Ws[k * HF + tc], acc);
        g_feat[n * HF + tc] = acc;
        float pl = acc * a_l, pr = acc * a_r;
#pragma unroll
        for (int o = 16; o; o >>= 1) {
            pl += __shfl_down_sync(0xffffffffu, pl, o);
            pr += __shfl_down_sync(0xffffffffu, pr, o);
        }
        if (lane == 0) { g_el[n * NH + w] = pl; g_er[n * NH + w] = pr; }
    }
}

// ---------------- K2: single-block scan over 50k counts ------------------------
__global__ void __launch_bounds__(1024) k_scan() {
    const int C = (N_NODES + 1023) / 1024;   // 49
    int t = threadIdx.x, lane = t & 31, wid = t >> 5;
    int base = t * C;
    int s = 0;
    for (int i = 0; i < C; i++) {
        int idx = base + i;
        if (idx < N_NODES) s += g_cnt[idx];
    }
    int v = s;
#pragma unroll
    for (int o = 1; o < 32; o <<= 1) {
        int n = __shfl_up_sync(0xffffffffu, v, o);
        if (lane >= o) v += n;
    }
    __shared__ int wsum[32];
    if (lane == 31) wsum[wid] = v;
    __syncthreads();
    if (wid == 0) {
        int w = wsum[lane];
#pragma unroll
        for (int o = 1; o < 32; o <<= 1) {
            int n = __shfl_up_sync(0xffffffffu, w, o);
            if (lane >= o) w += n;
        }
        wsum[lane] = w;
    }
    __syncthreads();
    int run = v - s + (wid ? wsum[wid - 1] : 0);
    for (int i = 0; i < C; i++) {
        int idx = base + i;
        if (idx < N_NODES) {
            int c = g_cnt[idx];
            g_rowp[idx] = run;
            g_cnt[idx]  = run;
            run += c;
        }
    }
    if (t == 0) g_rowp[N_NODES] = N_EDGES;
}

// ---------------- K3: CSR fill -------------------------------------------------
__global__ void __launch_bounds__(256) k_fill(
    const void* __restrict__ src, const void* __restrict__ dst)
{
    int e = blockIdx.x * blockDim.x + threadIdx.x;
    if (e >= N_EDGES) return;
    int is64 = g_idx64;
    int d = ldidx(dst, e, is64);
    int pos = atomicAdd(&g_cnt[d], 1);
    g_csrc[pos] = ldidx(src, e, is64);
}

// ---------------- K4: single-pass softmax aggregate (warp/node, 4-edge ILP) ----
__global__ void __launch_bounds__(256) k_aggr() {
    int n = blockIdx.x * 8 + (threadIdx.x >> 5);
    if (n >= N_NODES) return;
    int lane = threadIdx.x & 31;
    int hd = lane >> 3;
    int beg = g_rowp[n], end = g_rowp[n + 1];
    float er_h = g_er[n * NH + hd];

    float4 acc = make_float4(0.f, 0.f, 0.f, 0.f);
    float dsum = 0.f;
    int col = lane * 4;
    int j = beg;
    for (; j + 4 <= end; j += 4) {
        int s0 = g_csrc[j], s1 = g_csrc[j + 1], s2 = g_csrc[j + 2], s3 = g_csrc[j + 3];
        float l0 = g_el[s0 * NH + hd];
        float l1 = g_el[s1 * NH + hd];
        float l2 = g_el[s2 * NH + hd];
        float l3 = g_el[s3 * NH + hd];
        float4 f0 = *(const float4*)&g_feat[s0 * HF + col];
        float4 f1 = *(const float4*)&g_feat[s1 * HF + col];
        float4 f2 = *(const float4*)&g_feat[s2 * HF + col];
        float4 f3 = *(const float4*)&g_feat[s3 * HF + col];
        float e0 = __expf(lrelu(l0 + er_h));
        float e1 = __expf(lrelu(l1 + er_h));
        float e2 = __expf(lrelu(l2 + er_h));
        float e3 = __expf(lrelu(l3 + er_h));
        acc.x = fmaf(f0.x, e0, acc.x); acc.y = fmaf(f0.y, e0, acc.y);
        acc.z = fmaf(f0.z, e0, acc.z); acc.w = fmaf(f0.w, e0, acc.w);
        acc.x = fmaf(f1.x, e1, acc.x); acc.y = fmaf(f1.y, e1, acc.y);
        acc.z = fmaf(f1.z, e1, acc.z); acc.w = fmaf(f1.w, e1, acc.w);
        acc.x = fmaf(f2.x, e2, acc.x); acc.y = fmaf(f2.y, e2, acc.y);
        acc.z = fmaf(f2.z, e2, acc.z); acc.w = fmaf(f2.w, e2, acc.w);
        acc.x = fmaf(f3.x, e3, acc.x); acc.y = fmaf(f3.y, e3, acc.y);
        acc.z = fmaf(f3.z, e3, acc.z); acc.w = fmaf(f3.w, e3, acc.w);
        dsum += (e0 + e1) + (e2 + e3);
    }
    for (; j < end; j++) {
        int s = g_csrc[j];
        float ee = __expf(lrelu(g_el[s * NH + hd] + er_h));
        float4 f = *(const float4*)&g_feat[s * HF + col];
        acc.x = fmaf(f.x, ee, acc.x); acc.y = fmaf(f.y, ee, acc.y);
        acc.z = fmaf(f.z, ee, acc.z); acc.w = fmaf(f.w, ee, acc.w);
        dsum += ee;
    }
    float inv = (dsum > 0.f) ? 1.0f / dsum : 0.0f;
    acc.x *= inv; acc.y *= inv; acc.z *= inv; acc.w *= inv;
    *(float4*)&g_x[n * HF + col] = acc;
}

// ---------------- K5: GRU cell + ELU (128 nodes/block, 8 nodes/thread) ---------
#define W_PAD   132
#define WH_PAD  36
#define NODES_B 128

__global__ void __launch_bounds__(512) k_gru(
    const float* __restrict__ h,
    const float* __restrict__ Wih, const float* __restrict__ Whh,
    const float* __restrict__ bih, const float* __restrict__ bhh,
    float* __restrict__ out)
{
    extern __shared__ float sm[];
    float* sWih = sm;                         // [96][132]
    float* sWhh = sWih + G3 * W_PAD;          // [96][36]
    float* sbi  = sWhh + G3 * WH_PAD;         // 96
    float* sbh  = sbi + G3;                   // 96
    float* xs   = sbh + G3;                   // [128][128]
    float* hs   = xs + NODES_B * HF;          // [128][32]

    int t = threadIdx.x;
    for (int i = t; i < G3 * HF; i += 512) sWih[(i >> 7) * W_PAD + (i & 127)] = Wih[i];
    for (int i = t; i < G3 * FD; i += 512) sWhh[(i >> 5) * WH_PAD + (i & 31)] = Whh[i];
    if (t < G3) { sbi[t] = bih[t]; sbh[t] = bhh[t]; }

    int base = blockIdx.x * NODES_B;
    float4 z4 = make_float4(0.f, 0.f, 0.f, 0.f);
    float4* xs4 = (float4*)xs;
    float4* hs4 = (float4*)hs;
    for (int i = t; i < NODES_B * HF / 4; i += 512) {
        int n = base + (i >> 5);
        xs4[i] = (n < N_NODES) ? ((const float4*)g_x)[n * 32 + (i & 31)] : z4;
    }
    for (int i = t; i < NODES_B * FD / 4; i += 512) {
        int n = base + (i >> 3);
        hs4[i] = (n < N_NODES) ? ((const float4*)h)[n * 8 + (i & 7)] : z4;
    }
    __syncthreads();

    int oi = t & 31, ni = t >> 5;   // 16 warps, 8 nodes each
    float gr[8], gz[8], gn[8], hr[8], hz[8], hn[8];
#pragma unroll
    for (int j = 0; j < 8; j++) {
        gr[j] = sbi[oi]; gz[j] = sbi[32 + oi]; gn[j] = sbi[64 + oi];
        hr[j] = sbh[oi]; hz[j] = sbh[32 + oi]; hn[j] = sbh[64 + oi];
    }
    for (int k = 0; k < HF; k += 4) {
        float4 w0 = *(const float4*)&sWih[oi * W_PAD + k];
        float4 w1 = *(const float4*)&sWih[(32 + oi) * W_PAD + k];
        float4 w2 = *(const float4*)&sWih[(64 + oi) * W_PAD + k];
#pragma unroll
        for (int j = 0; j < 8; j++) {
            float4 xv = *(const float4*)&xs[(ni * 8 + j) * HF + k];
            gr[j] = fmaf(w0.x, xv.x, fmaf(w0.y, xv.y, fmaf(w0.z, xv.z, fmaf(w0.w, xv.w, gr[j]))));
            gz[j] = fmaf(w1.x, xv.x, fmaf(w1.y, xv.y, fmaf(w1.z, xv.z, fmaf(w1.w, xv.w, gz[j]))));
            gn[j] = fmaf(w2.x, xv.x, fmaf(w2.y, xv.y, fmaf(w2.z, xv.z, fmaf(w2.w, xv.w, gn[j]))));
        }
    }
    for (int k = 0; k < FD; k += 4) {
        float4 w0 = *(const float4*)&sWhh[oi * WH_PAD + k];
        float4 w1 = *(const float4*)&sWhh[(32 + oi) * WH_PAD + k];
        float4 w2 = *(const float4*)&sWhh[(64 + oi) * WH_PAD + k];
#pragma unroll
        for (int j = 0; j < 8; j++) {
            float4 hv = *(const float4*)&hs[(ni * 8 + j) * FD + k];
            hr[j] = fmaf(w0.x, hv.x, fmaf(w0.y, hv.y, fmaf(w0.z, hv.z, fmaf(w0.w, hv.w, hr[j]))));
            hz[j] = fmaf(w1.x, hv.x, fmaf(w1.y, hv.y, fmaf(w1.z, hv.z, fmaf(w1.w, hv.w, hz[j]))));
            hn[j] = fmaf(w2.x, hv.x, fmaf(w2.y, hv.y, fmaf(w2.z, hv.z, fmaf(w2.w, hv.w, hn[j]))));
        }
    }
#pragma unroll
    for (int j = 0; j < 8; j++) {
        int n = base + ni * 8 + j;
        if (n >= N_NODES) continue;
        float r  = 1.0f / (1.0f + __expf(-(gr[j] + hr[j])));
        float z  = 1.0f / (1.0f + __expf(-(gz[j] + hz[j])));
        float nn = tanhf(gn[j] + r * hn[j]);
        float hv = hs[(ni * 8 + j) * FD + oi];
        float hnew = (1.0f - z) * nn + z * hv;
        out[n * FD + oi] = hnew > 0.0f ? hnew : (__expf(hnew) - 1.0f);
    }
}

// ---------------- launch -------------------------------------------------------
extern "C" void kernel_launch(void* const* d_in, const int* in_sizes, int n_in,
                              void* d_out, int out_size)
{
    const float* h    = (const float*)d_in[0];
    const float* Wg   = (const float*)d_in[1];
    const float* al   = (const float*)d_in[2];
    const float* ar   = (const float*)d_in[3];
    const float* Wih  = (const float*)d_in[4];
    const float* Whh  = (const float*)d_in[5];
    const float* bih  = (const float*)d_in[6];
    const float* bhh  = (const float*)d_in[7];
    const void*  src  = d_in[8];
    const void*  dst  = d_in[9];
    float* out = (float*)d_out;

    static bool attr_set = false;
    size_t gru_smem = (size_t)(G3 * W_PAD + G3 * WH_PAD + 2 * G3 +
                               NODES_B * HF + NODES_B * FD) * sizeof(float);
    if (!attr_set) {
        cudaFuncSetAttribute(k_gru, cudaFuncAttributeMaxDynamicSharedMemorySize, (int)gru_smem);
        attr_set = true;
    }

    int hist_blocks = (N_EDGES + 255) / 256;
    k_init    <<<(N_NODES + 255) / 256, 256>>>((const unsigned*)dst);
    k_feathist<<<FEAT_BLOCKS + hist_blocks, 256>>>(h, Wg, al, ar, dst);
    k_scan    <<<1, 1024>>>();
    k_fill    <<<(N_EDGES + 255) / 256, 256>>>(src, dst);
    k_aggr    <<<(N_NODES + 7) / 8, 256>>>();
    k_gru     <<<(N_NODES + NODES_B - 1) / NODES_B, 512, gru_smem>>>(h, Wih, Whh, bih, bhh, out);
}